// round 4
// baseline (speedup 1.0000x reference)
#include <cuda_runtime.h>

// ---------------- problem constants ----------------
#define TSEQ   2048
#define BB     8
#define DMODEL 256
#define DINNER 512
#define DSTATE 16
#define DTRANK 16
#define DCONV  4
#define STATEDIM 128
#define ACTDIM 18
#define CH     32
#define NCHUNK (TSEQ / CH)          // 64
#define MROWS  (BB * TSEQ)          // 16384

// ---------------- scratch (static device globals; no allocation) ----------------
__device__ float g_W2[DINNER * STATEDIM];        // in_proj_x @ Ws      (512x128)
__device__ float g_wr2[DINNER];                  // in_proj_x @ Wr
__device__ float g_c2[DINNER];                   // in_proj_x @ (bs+br)
__device__ float g_posx[TSEQ * DINNER];          // pos_emb @ in_proj_x^T
__device__ float g_xpre[MROWS * DINNER];         // pre-conv x
__device__ float g_x[MROWS * DINNER];            // post conv+silu x
__device__ float g_xpw[64 * DINNER];             // x_proj_w padded to 64 rows
__device__ float g_dbc[MROWS * 64];              // [dtr(16) | B(16) | C(16) | pad]
__device__ float g_P[BB * NCHUNK * DINNER * DSTATE];
__device__ float g_cc[BB * NCHUNK * DINNER * DSTATE];
__device__ float g_yscan[BB * DINNER];
__device__ int   g_last[BB];

__device__ __forceinline__ float softplusf(float v) {
    return (v > 20.f) ? v : log1pf(__expf(v));
}
__device__ __forceinline__ float siluf(float v) {
    return v / (1.f + __expf(-v));
}

// ---------------- last valid index per batch ----------------
__global__ void k_last(const float* __restrict__ mask) {
    int b = blockIdx.x, lane = threadIdx.x;
    float s = 0.f;
    for (int t = lane; t < TSEQ; t += 32) s += mask[b * TSEQ + t];
    #pragma unroll
    for (int o = 16; o; o >>= 1) s += __shfl_xor_sync(0xffffffffu, s, o);
    if (lane == 0) {
        int vi = (int)fmaxf(s, 1.f);
        int li = vi - 1;
        if (li < 0) li = 0;
        if (li > TSEQ - 1) li = TSEQ - 1;
        g_last[b] = li;
    }
}

// ---------------- precompute fused in_proj weights ----------------
// W2[d,k] = sum_j in_proj_w[d,j] * Ws[j,k];  wr2[d] = in_proj_w[d,:]·Wr; c2[d] = in_proj_w[d,:]·(bs+br)
__global__ void k_prep_w2(const float* __restrict__ inpw, const float* __restrict__ Ws,
                          const float* __restrict__ bs, const float* __restrict__ br,
                          const float* __restrict__ Wr) {
    int d = blockIdx.x, tid = threadIdx.x;            // 512 blocks, 128 threads
    __shared__ float inw[DMODEL];
    __shared__ float r1[128], r2[128];
    inw[tid]       = inpw[d * DMODEL + tid];
    inw[tid + 128] = inpw[d * DMODEL + tid + 128];
    __syncthreads();
    float acc = 0.f;
    #pragma unroll 4
    for (int j = 0; j < DMODEL; ++j) acc = fmaf(inw[j], Ws[j * STATEDIM + tid], acc);
    g_W2[d * STATEDIM + tid] = acc;
    float a1 = 0.f, a2 = 0.f;
    for (int j = tid; j < DMODEL; j += 128) {
        a1 = fmaf(inw[j], bs[j] + br[j], a1);
        a2 = fmaf(inw[j], Wr[j], a2);
    }
    r1[tid] = a1; r2[tid] = a2;
    __syncthreads();
    for (int off = 64; off; off >>= 1) {
        if (tid < off) { r1[tid] += r1[tid + off]; r2[tid] += r2[tid + off]; }
        __syncthreads();
    }
    if (tid == 0) { g_c2[d] = r1[0]; g_wr2[d] = r2[0]; }
}

// ---------------- pad x_proj_w (48x512) -> (64x512) with zero rows ----------------
__global__ void k_pad_xproj(const float* __restrict__ xw) {
    int i = blockIdx.x * 256 + threadIdx.x;
    if (i < 64 * DINNER) {
        int r = i / DINNER;
        g_xpw[i] = (r < 48) ? xw[i] : 0.f;
    }
}

// ---------------- generic tiled SGEMM: C[M,N] = A[M,K] @ W[N,K]^T (+ epilogue) ----------------
// BM=BN=64, BK=16, 256 threads, 4x4 per thread. Requires M%64==0, N%64==0, K%16==0.
template<int EPI>
__device__ __forceinline__ void gemm_body(
    const float* __restrict__ A, const float* __restrict__ W, float* __restrict__ C,
    int M, int N, int K, int lda, int ldw, int ldc,
    const float* __restrict__ rtg, const float* __restrict__ mask)
{
    __shared__ float As[16][64];
    __shared__ float Bs[16][64];
    int tid = threadIdx.x;
    int tx = tid & 15, ty = tid >> 4;
    int m0 = blockIdx.y * 64, n0 = blockIdx.x * 64;
    int lr = tid >> 2;            // 0..63
    int lc = (tid & 3) * 4;       // 0,4,8,12
    const float* Ap = A + (size_t)(m0 + lr) * lda + lc;
    const float* Wp = W + (size_t)(n0 + lr) * ldw + lc;
    float acc[4][4] = {};
    for (int k0 = 0; k0 < K; k0 += 16) {
        float4 av = *reinterpret_cast<const float4*>(Ap + k0);
        float4 wv = *reinterpret_cast<const float4*>(Wp + k0);
        __syncthreads();
        As[lc + 0][lr] = av.x; As[lc + 1][lr] = av.y; As[lc + 2][lr] = av.z; As[lc + 3][lr] = av.w;
        Bs[lc + 0][lr] = wv.x; Bs[lc + 1][lr] = wv.y; Bs[lc + 2][lr] = wv.z; Bs[lc + 3][lr] = wv.w;
        __syncthreads();
        #pragma unroll
        for (int kk = 0; kk < 16; ++kk) {
            float4 a = *reinterpret_cast<const float4*>(&As[kk][ty * 4]);
            float4 b = *reinterpret_cast<const float4*>(&Bs[kk][tx * 4]);
            acc[0][0] = fmaf(a.x, b.x, acc[0][0]); acc[0][1] = fmaf(a.x, b.y, acc[0][1]);
            acc[0][2] = fmaf(a.x, b.z, acc[0][2]); acc[0][3] = fmaf(a.x, b.w, acc[0][3]);
            acc[1][0] = fmaf(a.y, b.x, acc[1][0]); acc[1][1] = fmaf(a.y, b.y, acc[1][1]);
            acc[1][2] = fmaf(a.y, b.z, acc[1][2]); acc[1][3] = fmaf(a.y, b.w, acc[1][3]);
            acc[2][0] = fmaf(a.z, b.x, acc[2][0]); acc[2][1] = fmaf(a.z, b.y, acc[2][1]);
            acc[2][2] = fmaf(a.z, b.z, acc[2][2]); acc[2][3] = fmaf(a.z, b.w, acc[2][3]);
            acc[3][0] = fmaf(a.w, b.x, acc[3][0]); acc[3][1] = fmaf(a.w, b.y, acc[3][1]);
            acc[3][2] = fmaf(a.w, b.z, acc[3][2]); acc[3][3] = fmaf(a.w, b.w, acc[3][3]);
        }
    }
    int n = n0 + tx * 4;
    #pragma unroll
    for (int i = 0; i < 4; ++i) {
        int m = m0 + ty * 4 + i;
        float4 out;
        if (EPI == 1) {
            int t = m & (TSEQ - 1);
            float rv = rtg[m], mk = mask[m];
            out.x = (acc[i][0] + g_posx[t * DINNER + n + 0] + rv * g_wr2[n + 0] + g_c2[n + 0]) * mk;
            out.y = (acc[i][1] + g_posx[t * DINNER + n + 1] + rv * g_wr2[n + 1] + g_c2[n + 1]) * mk;
            out.z = (acc[i][2] + g_posx[t * DINNER + n + 2] + rv * g_wr2[n + 2] + g_c2[n + 2]) * mk;
            out.w = (acc[i][3] + g_posx[t * DINNER + n + 3] + rv * g_wr2[n + 3] + g_c2[n + 3]) * mk;
        } else {
            out.x = acc[i][0]; out.y = acc[i][1]; out.z = acc[i][2]; out.w = acc[i][3];
        }
        *reinterpret_cast<float4*>(C + (size_t)m * ldc + n) = out;
    }
}

__global__ __launch_bounds__(256) void k_gemm_posx(const float* __restrict__ pos,
                                                   const float* __restrict__ inpw) {
    gemm_body<0>(pos, inpw, g_posx, TSEQ, DINNER, DMODEL, DMODEL, DMODEL, DINNER, nullptr, nullptr);
}
__global__ __launch_bounds__(256) void k_gemm_xpre(const float* __restrict__ state,
                                                   const float* __restrict__ rtg,
                                                   const float* __restrict__ mask) {
    gemm_body<1>(state, g_W2, g_xpre, MROWS, DINNER, STATEDIM, STATEDIM, STATEDIM, DINNER, rtg, mask);
}
__global__ __launch_bounds__(256) void k_gemm_dbc() {
    gemm_body<0>(g_x, g_xpw, g_dbc, MROWS, 64, DINNER, DINNER, DINNER, 64, nullptr, nullptr);
}

// ---------------- causal depthwise conv + SiLU ----------------
__global__ void k_conv(const float* __restrict__ conv_w, const float* __restrict__ conv_b) {
    int idx = blockIdx.x * 256 + threadIdx.x;        // < MROWS*DINNER
    int d = idx & (DINNER - 1);
    int row = idx >> 9;
    int t = row & (TSEQ - 1);
    float4 cw = reinterpret_cast<const float4*>(conv_w)[d];
    const float* xp = g_xpre + (size_t)row * DINNER + d;
    float v0 = (t >= 3) ? xp[-3 * DINNER] : 0.f;
    float v1 = (t >= 2) ? xp[-2 * DINNER] : 0.f;
    float v2 = (t >= 1) ? xp[-1 * DINNER] : 0.f;
    float v3 = xp[0];
    float acc = conv_b[d];
    acc = fmaf(v0, cw.x, acc);
    acc = fmaf(v1, cw.y, acc);
    acc = fmaf(v2, cw.z, acc);
    acc = fmaf(v3, cw.w, acc);
    g_x[idx] = siluf(acc);
}

// ---------------- scan phase 1: per-chunk (P, c) with fused dt computation ----------------
// grid (DINNER/32, NCHUNK, BB), 512 threads. thread: dl = tid>>4 (d within tile), s = tid&15.
__global__ __launch_bounds__(512) void k_scan1(const float* __restrict__ dt_proj_w,
                                               const float* __restrict__ dt_proj_b,
                                               const float* __restrict__ A_log) {
    __shared__ float sh_x[CH][32];
    __shared__ float sh_dt[CH][32];
    __shared__ float sh_dtr[CH][16];
    __shared__ float sh_B[CH][16];
    __shared__ float sh_dtW[16][32];   // [r][dl]
    __shared__ float sh_dtb[32];

    int tid = threadIdx.x;
    int dl = tid >> 4, s = tid & 15;
    int d0 = blockIdx.x * 32;
    int t0 = blockIdx.y * CH;
    int b  = blockIdx.z;
    size_t rowbase = (size_t)b * TSEQ + t0;

    for (int i = tid; i < CH * 32; i += 512) {
        int t = i >> 5, j = i & 31;
        sh_x[t][j] = g_x[(rowbase + t) * DINNER + d0 + j];
        float v = g_dbc[(rowbase + t) * 64 + j];
        if (j < 16) sh_dtr[t][j] = v; else sh_B[t][j - 16] = v;
    }
    sh_dtW[tid & 15][tid >> 4] = dt_proj_w[d0 * 16 + tid];
    if (tid < 32) sh_dtb[tid] = dt_proj_b[d0 + tid];
    float Aval = -__expf(A_log[d0 * DSTATE + tid]);
    __syncthreads();

    // dt tile: softplus(dtr @ dtW^T + b)
    for (int i = tid; i < CH * 32; i += 512) {
        int t = i >> 5, j = i & 31;
        float v = sh_dtb[j];
        #pragma unroll
        for (int r = 0; r < 16; ++r) v = fmaf(sh_dtr[t][r], sh_dtW[r][j], v);
        sh_dt[t][j] = softplusf(v);
    }
    __syncthreads();

    float rdt[CH], rdtx[CH];
    #pragma unroll
    for (int t = 0; t < CH; ++t) {
        rdt[t]  = sh_dt[t][dl];
        rdtx[t] = rdt[t] * sh_x[t][dl];
    }
    float P = 1.f, c = 0.f;
    #pragma unroll
    for (int t = 0; t < CH; ++t) {
        float a = __expf(rdt[t] * Aval);
        c = fmaf(a, c, rdtx[t] * sh_B[t][s]);
        P *= a;
    }
    size_t base = ((size_t)(b * NCHUNK + blockIdx.y)) * (DINNER * DSTATE) + d0 * DSTATE + tid;
    g_P[base]  = P;
    g_cc[base] = c;
}

// ---------------- scan phase 2: fold chunks, reduce over states -> y_scan ----------------
__global__ void k_scan2(const float* __restrict__ dt_proj_w,
                        const float* __restrict__ dt_proj_b,
                        const float* __restrict__ A_log) {
    int gid = blockIdx.x * 256 + threadIdx.x;
    int b = gid >> 13;
    int ds = gid & 8191;
    int d = ds >> 4, s = ds & 15;
    int last = g_last[b];
    int L = last + 1;
    int kfull = L / CH, rem = L % CH;

    float h = 0.f;
    const size_t stride = DINNER * DSTATE;
    size_t idx = (size_t)b * NCHUNK * stride + ds;
    for (int ch = 0; ch < kfull; ++ch) {
        h = fmaf(g_P[idx], h, g_cc[idx]);
        idx += stride;
    }
    if (rem) {
        float Aval = -__expf(A_log[d * DSTATE + s]);
        for (int t = kfull * CH; t <= last; ++t) {
            size_t row = (size_t)b * TSEQ + t;
            float v = dt_proj_b[d];
            #pragma unroll
            for (int r = 0; r < 16; ++r) v = fmaf(g_dbc[row * 64 + r], dt_proj_w[d * 16 + r], v);
            float dt = softplusf(v);
            float a = __expf(dt * Aval);
            h = fmaf(a, h, dt * g_x[row * DINNER + d] * g_dbc[row * 64 + 16 + s]);
        }
    }
    float Cv = g_dbc[((size_t)b * TSEQ + last) * 64 + 32 + s];
    float p = h * Cv;
    p += __shfl_xor_sync(0xffffffffu, p, 8);
    p += __shfl_xor_sync(0xffffffffu, p, 4);
    p += __shfl_xor_sync(0xffffffffu, p, 2);
    p += __shfl_xor_sync(0xffffffffu, p, 1);
    if (s == 0) g_yscan[b * DINNER + d] = p;
}

// ---------------- final: token_last, z-gate, out_proj, layernorm, head ----------------
__global__ void k_final(const float* __restrict__ state, const float* __restrict__ rtg,
                        const float* __restrict__ mask, const float* __restrict__ Ws,
                        const float* __restrict__ bs, const float* __restrict__ Wr,
                        const float* __restrict__ br, const float* __restrict__ pos_emb,
                        const float* __restrict__ inpw, const float* __restrict__ Dv,
                        const float* __restrict__ outw, const float* __restrict__ lng,
                        const float* __restrict__ lnb, const float* __restrict__ hw,
                        const float* __restrict__ hb, float* __restrict__ out) {
    int b = blockIdx.x, tid = threadIdx.x;   // 256 threads
    __shared__ float st[STATEDIM];
    __shared__ float tok[DMODEL];
    __shared__ float ybuf[DINNER];
    __shared__ float hid[DMODEL];
    __shared__ float red1[8], red2[8];

    int last = g_last[b];
    size_t row = (size_t)b * TSEQ + last;
    if (tid < STATEDIM) st[tid] = state[row * STATEDIM + tid];
    __syncthreads();

    // token at last index
    {
        float acc = bs[tid] + br[tid] + rtg[row] * Wr[tid] + pos_emb[(size_t)last * DMODEL + tid];
        const float* w = Ws + (size_t)tid * STATEDIM;
        #pragma unroll 4
        for (int k = 0; k < STATEDIM; ++k) acc = fmaf(st[k], w[k], acc);
        tok[tid] = acc * mask[row];
    }
    __syncthreads();

    // z gate and gated y
    for (int d = tid; d < DINNER; d += 256) {
        float z = 0.f;
        const float* w = inpw + (size_t)(DINNER + d) * DMODEL;
        #pragma unroll 4
        for (int k = 0; k < DMODEL; ++k) z = fmaf(tok[k], w[k], z);
        float yv = g_yscan[b * DINNER + d] + g_x[row * DINNER + d] * Dv[d];
        ybuf[d] = yv * siluf(z);
    }
    __syncthreads();

    // out_proj
    {
        float acc = 0.f;
        const float* w = outw + (size_t)tid * DINNER;
        #pragma unroll 4
        for (int k = 0; k < DINNER; ++k) acc = fmaf(ybuf[k], w[k], acc);
        hid[tid] = acc;
    }
    __syncthreads();

    // layernorm over 256
    float v = hid[tid];
    float sum = v;
    #pragma unroll
    for (int o = 16; o; o >>= 1) sum += __shfl_xor_sync(0xffffffffu, sum, o);
    if ((tid & 31) == 0) red1[tid >> 5] = sum;
    __syncthreads();
    if (tid == 0) {
        float s = 0.f;
        #pragma unroll
        for (int i = 0; i < 8; ++i) s += red1[i];
        red1[0] = s * (1.f / DMODEL);
    }
    __syncthreads();
    float mu = red1[0];
    float dvv = v - mu;
    float sq = dvv * dvv;
    #pragma unroll
    for (int o = 16; o; o >>= 1) sq += __shfl_xor_sync(0xffffffffu, sq, o);
    if ((tid & 31) == 0) red2[tid >> 5] = sq;
    __syncthreads();
    if (tid == 0) {
        float s = 0.f;
        #pragma unroll
        for (int i = 0; i < 8; ++i) s += red2[i];
        red2[0] = rsqrtf(s * (1.f / DMODEL) + 1e-5f);
    }
    __syncthreads();
    float hn = dvv * red2[0] * lng[tid] + lnb[tid];
    __syncthreads();
    hid[tid] = hn;
    __syncthreads();

    if (tid < ACTDIM) {
        float acc = hb[tid];
        const float* w = hw + (size_t)tid * DMODEL;
        #pragma unroll 4
        for (int k = 0; k < DMODEL; ++k) acc = fmaf(hid[k], w[k], acc);
        out[b * ACTDIM + tid] = acc;
    }
}

// ---------------- launch ----------------
extern "C" void kernel_launch(void* const* d_in, const int* in_sizes, int n_in,
                              void* d_out, int out_size) {
    const float* state = (const float*)d_in[0];
    const float* rtg   = (const float*)d_in[1];
    const float* mask  = (const float*)d_in[2];
    const float* Ws    = (const float*)d_in[3];
    const float* bs    = (const float*)d_in[4];
    const float* Wr    = (const float*)d_in[5];
    const float* br    = (const float*)d_in[6];
    const float* pos   = (const float*)d_in[7];
    const float* inpw  = (const float*)d_in[8];
    const float* convw = (const float*)d_in[9];
    const float* convb = (const float*)d_in[10];
    const float* xpw   = (const float*)d_in[11];
    const float* dtw   = (const float*)d_in[12];
    const float* dtb   = (const float*)d_in[13];
    const float* alog  = (const float*)d_in[14];
    const float* Dv    = (const float*)d_in[15];
    const float* outw  = (const float*)d_in[16];
    const float* lng   = (const float*)d_in[17];
    const float* lnb   = (const float*)d_in[18];
    const float* hw    = (const float*)d_in[19];
    const float* hb    = (const float*)d_in[20];
    float* out = (float*)d_out;

    k_last<<<BB, 32>>>(mask);
    k_prep_w2<<<DINNER, 128>>>(inpw, Ws, bs, br, Wr);
    k_pad_xproj<<<(64 * DINNER + 255) / 256, 256>>>(xpw);
    k_gemm_posx<<<dim3(DINNER / 64, TSEQ / 64), 256>>>(pos, inpw);
    k_gemm_xpre<<<dim3(DINNER / 64, MROWS / 64), 256>>>(state, rtg, mask);
    k_conv<<<(MROWS * DINNER) / 256, 256>>>(convw, convb);
    k_gemm_dbc<<<dim3(1, MROWS / 64), 256>>>();
    k_scan1<<<dim3(DINNER / 32, NCHUNK, BB), 512>>>(dtw, dtb, alog);
    k_scan2<<<(BB * DINNER * DSTATE) / 256, 256>>>(dtw, dtb, alog);
    k_final<<<BB, 256>>>(state, rtg, mask, Ws, bs, Wr, br, pos, inpw,
                         Dv, outw, lng, lnb, hw, hb, out);
}